// round 15
// baseline (speedup 1.0000x reference)
#include <cuda_runtime.h>
#include <cuda_fp16.h>
#include <cstdint>

// ============================================================================
// HQQ grouped int4 GEMM, sm_103 base target.
//
// R15: two-kernel graph:
//   1. prep : merged streaming dequant (W = fp16(q*s + z - 8s), k-major) and
//             x -> fp16 conversion.
//   2. main : CTA tile 128x256x64, 512 thr, warp grid 4x4 (32x64 warp tiles),
//             3-stage cp.async ring with depth-2 (wait_group<1>),
//             A normal ldsm, B ldmatrix.trans.
// ============================================================================

namespace {

constexpr int kE   = 8;
constexpr int kT   = 2048;
constexpr int kIN  = 2048;
constexpr int kOUT = 2048;
constexpr int kG   = 32;

constexpr int kBM  = 128;
constexpr int kBN  = 256;
constexpr int kBK  = 64;
constexpr int kNCh = kIN / kBK;           // 32
constexpr int kThreads = 512;             // 16 warps, grid 4(m) x 4(n)

constexpr int kATileB = kBM * kBK * 2;    // 16 KB (rows m, 128B of k)
constexpr int kBRowB  = kBN * 2;          // 512B per k-row
constexpr int kBTileB = kBK * kBRowB;     // 32 KB (rows k, 512B of n)
constexpr int kStageB = kATileB + kBTileB;          // 49152
constexpr int kSmemB  = 3 * kStageB;                // 147456 (3-stage ring)

constexpr int kDqBlocks = kE * (kIN / 8) * (kOUT / 1024);  // 4096
constexpr int kCvBlocks = (kT * kIN) / (256 * 16);         // 1024

__device__ __half g_xh[(size_t)kT * kIN];
__device__ __half g_W[(size_t)kE * kIN * kOUT];     // k-major, same layout as q

// ---------------------------------------------------------------------------

__device__ __forceinline__ uint32_t smem_u32(const void* p) {
  uint32_t a;
  asm("{ .reg .u64 t; cvta.to.shared.u64 t, %1; cvt.u32.u64 %0, t; }" : "=r"(a) : "l"(p));
  return a;
}

__device__ __forceinline__ uint32_t pack_f16x2(float lo, float hi) {
  uint32_t r;
  asm("cvt.rn.f16x2.f32 %0, %1, %2;" : "=r"(r) : "f"(hi), "f"(lo));
  return r;
}

__device__ __forceinline__ uint32_t sw128(uint32_t off) {
  return off ^ ((off >> 3) & 0x70);
}

__device__ __forceinline__ void ldsm_x4(uint32_t* r, uint32_t addr) {
  asm volatile("ldmatrix.sync.aligned.m8n8.x4.shared.b16 {%0,%1,%2,%3}, [%4];"
               : "=r"(r[0]), "=r"(r[1]), "=r"(r[2]), "=r"(r[3]) : "r"(addr));
}

__device__ __forceinline__ void ldsm_x4_trans(uint32_t* r, uint32_t addr) {
  asm volatile("ldmatrix.sync.aligned.m8n8.x4.trans.shared.b16 {%0,%1,%2,%3}, [%4];"
               : "=r"(r[0]), "=r"(r[1]), "=r"(r[2]), "=r"(r[3]) : "r"(addr));
}

__device__ __forceinline__ void mma_f16(float* c, const uint32_t* a,
                                        uint32_t b0, uint32_t b1) {
  asm volatile(
      "mma.sync.aligned.m16n8k16.row.col.f32.f16.f16.f32 "
      "{%0,%1,%2,%3}, {%4,%5,%6,%7}, {%8,%9}, {%0,%1,%2,%3};"
      : "+f"(c[0]), "+f"(c[1]), "+f"(c[2]), "+f"(c[3])
      : "r"(a[0]), "r"(a[1]), "r"(a[2]), "r"(a[3]), "r"(b0), "r"(b1));
}

__device__ __forceinline__ void cp16(uint32_t smem_addr, const void* gmem,
                                     uint32_t src_bytes) {
  asm volatile("cp.async.cg.shared.global [%0], [%1], 16, %2;"
               :: "r"(smem_addr), "l"(gmem), "r"(src_bytes) : "memory");
}

#define CP_COMMIT() asm volatile("cp.async.commit_group;" ::: "memory")
#define CP_WAIT0()  asm volatile("cp.async.wait_group 0;" ::: "memory")
#define CP_WAIT1()  asm volatile("cp.async.wait_group 1;" ::: "memory")

// ---------------------------------------------------------------------------
// Kernel 1: merged prepass.  Blocks [0, kDqBlocks): dequant; rest: convert x.
// ---------------------------------------------------------------------------

__global__ void __launch_bounds__(256)
prep_kernel(const float* __restrict__ x, const int* __restrict__ qw,
            const float* __restrict__ snz) {
  const int tid = threadIdx.x;
  const int b   = blockIdx.x;

  if (b < kDqBlocks) {
    const int e   = b >> 9;
    const int rem = b & 511;
    const int k0  = (rem >> 1) * 8;
    const int n   = ((rem & 1) * 256 + tid) * 4;
    const int g   = k0 >> 6;

    const float* sp = snz + (((size_t)e * kG + g) * kOUT + n) * 2;
    const float4 sa = *(const float4*)(sp);
    const float4 sb = *(const float4*)(sp + 4);
    const float s0 = sa.x, zp0 = fmaf(-8.f, sa.x, sa.y);
    const float s1 = sa.z, zp1 = fmaf(-8.f, sa.z, sa.w);
    const float s2 = sb.x, zp2 = fmaf(-8.f, sb.x, sb.y);
    const float s3 = sb.z, zp3 = fmaf(-8.f, sb.z, sb.w);

#pragma unroll
    for (int j = 0; j < 8; j++) {
      const size_t row = (size_t)e * kIN + k0 + j;
      const int4 q = *(const int4*)(qw + row * kOUT + n);
      uint2 o;
      o.x = pack_f16x2(fmaf((float)q.x, s0, zp0), fmaf((float)q.y, s1, zp1));
      o.y = pack_f16x2(fmaf((float)q.z, s2, zp2), fmaf((float)q.w, s3, zp3));
      *(uint2*)(&g_W[row * kOUT + n]) = o;
    }
  } else {
    const size_t base = ((size_t)(b - kDqBlocks) * 256 + tid) * 16;
#pragma unroll
    for (int i = 0; i < 4; i++) {
      const float4 v = *(const float4*)(x + base + i * 4);
      uint2 o;
      o.x = pack_f16x2(v.x, v.y);
      o.y = pack_f16x2(v.z, v.w);
      *(uint2*)(&g_xh[base + i * 4]) = o;
    }
  }
}

// ---------------------------------------------------------------------------
// Kernel 2: main GEMM
// ---------------------------------------------------------------------------

__global__ void __launch_bounds__(kThreads, 1)
hqq_mma_kernel(const int* __restrict__ tpe, float* __restrict__ out) {
  extern __shared__ __align__(1024) char smem[];
  const int tid = threadIdx.x;
  const int wid = tid >> 5;
  const int l   = tid & 31;

  const int e  = blockIdx.z;
  const int nt = blockIdx.x;
  const int mt = blockIdx.y;

  int off = 0, cnt = 0;
#pragma unroll
  for (int i = 0; i < kE; i++) {
    int c = __ldg(&tpe[i]);
    if (i < e) off += c;
    if (i == e) cnt = c;
  }
  if (mt * kBM >= cnt) return;

  const int row0  = off + mt * kBM;
  const int nrows = min(kBM, cnt - mt * kBM);
  const int n0    = nt * kBN;

  const uint32_t sbase = smem_u32(smem);

  // ---- fragment addressing (warp grid 4x4, warp tile 32x64) ----
  const int wm = wid >> 2;                 // 0..3
  const int wn = wid & 3;                  // 0..3
  const int bj = l & 7;

  uint32_t aRow[2], aXor[2];
#pragma unroll
  for (int mi = 0; mi < 2; mi++) {
    const int row = wm * 32 + (l & 15) + mi * 16;
    aRow[mi] = (uint32_t)(row * 128);
    aXor[mi] = (uint32_t)((row & 7) << 4);
  }
  const uint32_t aSeg = (uint32_t)((l >> 4) * 16);

  const int bkoff = ((l >> 3) & 1) * 8 + bj;
  const uint32_t bBase = (uint32_t)(bkoff * kBRowB);
  uint32_t bChunk[4];
#pragma unroll
  for (int ni2 = 0; ni2 < 4; ni2++)
    bChunk[ni2] = (uint32_t)(((wn * 8 + ni2 * 2 + (l >> 4)) ^ bj) * 16);

  const __half* xh_base = &g_xh[0];
  const __half* w_base  = &g_W[(size_t)e * kIN * kOUT];

  auto issue_stage = [&](int ch, uint32_t st) {
    const int k0 = ch * kBK;
    // A: 1024 segs: g = i*512+tid -> m = g>>3, ks8 = g&7
#pragma unroll
    for (int i = 0; i < 2; i++) {
      const int g = i * 512 + tid;
      const int m = g >> 3, ks8 = g & 7;
      cp16(st + sw128((uint32_t)(m * 128 + ks8 * 16)),
           xh_base + (size_t)(row0 + m) * kIN + k0 + ks8 * 8,
           (m < nrows) ? 16u : 0u);
    }
    // B: 2048 segs: g = i*512+tid -> krow = g>>5, nchunk = g&31
    const uint32_t stB = st + kATileB;
#pragma unroll
    for (int i = 0; i < 4; i++) {
      const int g = i * 512 + tid;
      const int krow = g >> 5, nchunk = g & 31;
      cp16(stB + (uint32_t)(krow * kBRowB + ((nchunk ^ (krow & 7)) * 16)),
           w_base + (size_t)(k0 + krow) * kOUT + n0 + nchunk * 8, 16u);
    }
    CP_COMMIT();
  };

  float mast[64];
#pragma unroll
  for (int i = 0; i < 64; i++) mast[i] = 0.f;

  auto compute_stage = [&](uint32_t base) {
    const uint32_t baseB = base + kATileB + bBase;
#pragma unroll
    for (int ks = 0; ks < 4; ks++) {
      uint32_t Af[2][4];
      const uint32_t kterm = (uint32_t)(ks * 32) + aSeg;
#pragma unroll
      for (int mi = 0; mi < 2; mi++)
        ldsm_x4(Af[mi], base + aRow[mi] + (kterm ^ aXor[mi]));
      const uint32_t bK = baseB + (uint32_t)(ks * 16 * kBRowB);
#pragma unroll
      for (int ni2 = 0; ni2 < 4; ni2++) {
        uint32_t r[4];
        ldsm_x4_trans(r, bK + bChunk[ni2]);
#pragma unroll
        for (int mi = 0; mi < 2; mi++) {
          mma_f16(&mast[(mi * 8 + ni2 * 2) * 4],     Af[mi], r[0], r[1]);
          mma_f16(&mast[(mi * 8 + ni2 * 2 + 1) * 4], Af[mi], r[2], r[3]);
        }
      }
    }
  };

  // ---- 3-stage ring, depth-2 cp.async pipeline ----
  uint32_t stg0 = sbase, stg1 = sbase + kStageB, stg2 = sbase + 2 * kStageB;

  issue_stage(0, stg0);
  issue_stage(1, stg1);

  for (int ch = 0; ch < kNCh; ch++) {
    CP_WAIT1();            // stage ch landed (last committed is ch+1 / empty)
    __syncthreads();       // visible to all; compute(ch-1) done -> stg2 free
    if (ch + 2 < kNCh) issue_stage(ch + 2, stg2);
    else CP_COMMIT();      // empty group keeps wait_group<1> accounting right
    compute_stage(stg0);
    // rotate ring
    const uint32_t t = stg0; stg0 = stg1; stg1 = stg2; stg2 = t;
  }

  // ---- epilogue ----
#pragma unroll
  for (int mi = 0; mi < 2; mi++) {
#pragma unroll
    for (int ni = 0; ni < 8; ni++) {
      const float* c = &mast[(mi * 8 + ni) * 4];
      const int r0  = wm * 32 + mi * 16 + (l >> 2);
      const int col = n0 + wn * 64 + ni * 8 + (l & 3) * 2;
      if (r0 < nrows)
        *(float2*)(out + (size_t)(row0 + r0) * kOUT + col) = make_float2(c[0], c[1]);
      if (r0 + 8 < nrows)
        *(float2*)(out + (size_t)(row0 + r0 + 8) * kOUT + col) = make_float2(c[2], c[3]);
    }
  }
}

}  // namespace

// ---------------------------------------------------------------------------

extern "C" void kernel_launch(void* const* d_in, const int* in_sizes, int n_in,
                              void* d_out, int out_size) {
  (void)in_sizes; (void)n_in; (void)out_size;
  const float* x   = (const float*)d_in[0];
  const int*   qw  = (const int*)d_in[1];
  const float* snz = (const float*)d_in[2];
  const int*   tpe = (const int*)d_in[3];
  float* out = (float*)d_out;

  (void)cudaFuncSetAttribute(hqq_mma_kernel,
                             cudaFuncAttributeMaxDynamicSharedMemorySize, kSmemB);

  prep_kernel<<<kDqBlocks + kCvBlocks, 256>>>(x, qw, snz);
  dim3 grid(kOUT / kBN, kT / kBM, kE);   // (8, 16, 8); empty m-tiles early-exit
  hqq_mma_kernel<<<grid, kThreads, kSmemB>>>(tpe, out);
}

// round 16
// speedup vs baseline: 1.4543x; 1.4543x over previous
#include <cuda_runtime.h>
#include <cuda_fp16.h>
#include <cstdint>

// ============================================================================
// HQQ grouped int4 GEMM, sm_103 base target.
//
// R16: two-kernel graph:
//   1. prep : merged streaming dequant (W = fp16(q*s + z - 8s), k-major) and
//             x -> fp16 conversion.  (unchanged from R14)
//   2. main : CTA tile 64x256, BK=32, 256 thr (warp grid 2x4, 32x64 warp
//             tiles), 2 CTAs/SM, 4-stage cp.async ring with prefetch depth 3
//             (wait_group<2>).  A normal ldsm (64B rows, slot swizzle),
//             B ldmatrix.trans (512B rows, chunk-XOR swizzle).
// ============================================================================

namespace {

constexpr int kE   = 8;
constexpr int kT   = 2048;
constexpr int kIN  = 2048;
constexpr int kOUT = 2048;
constexpr int kG   = 32;

constexpr int kBM  = 64;
constexpr int kBN  = 256;
constexpr int kBK  = 32;
constexpr int kNCh = kIN / kBK;           // 64
constexpr int kThreads = 256;             // 8 warps, grid 2(m) x 4(n)

constexpr int kARowB  = kBK * 2;          // 64B per m-row
constexpr int kATileB = kBM * kARowB;     // 4 KB
constexpr int kBRowB  = kBN * 2;          // 512B per k-row
constexpr int kBTileB = kBK * kBRowB;     // 16 KB
constexpr int kStageB = kATileB + kBTileB;          // 20480
constexpr int kNStage = 4;
constexpr int kSmemB  = kNStage * kStageB;          // 81920 (x2 CTAs = 160KB)

constexpr int kDqBlocks = kE * (kIN / 8) * (kOUT / 1024);  // 4096
constexpr int kCvBlocks = (kT * kIN) / (256 * 16);         // 1024

__device__ __half g_xh[(size_t)kT * kIN];
__device__ __half g_W[(size_t)kE * kIN * kOUT];     // k-major, same layout as q

// ---------------------------------------------------------------------------

__device__ __forceinline__ uint32_t smem_u32(const void* p) {
  uint32_t a;
  asm("{ .reg .u64 t; cvta.to.shared.u64 t, %1; cvt.u32.u64 %0, t; }" : "=r"(a) : "l"(p));
  return a;
}

__device__ __forceinline__ uint32_t pack_f16x2(float lo, float hi) {
  uint32_t r;
  asm("cvt.rn.f16x2.f32 %0, %1, %2;" : "=r"(r) : "f"(hi), "f"(lo));
  return r;
}

__device__ __forceinline__ void ldsm_x4(uint32_t* r, uint32_t addr) {
  asm volatile("ldmatrix.sync.aligned.m8n8.x4.shared.b16 {%0,%1,%2,%3}, [%4];"
               : "=r"(r[0]), "=r"(r[1]), "=r"(r[2]), "=r"(r[3]) : "r"(addr));
}

__device__ __forceinline__ void ldsm_x4_trans(uint32_t* r, uint32_t addr) {
  asm volatile("ldmatrix.sync.aligned.m8n8.x4.trans.shared.b16 {%0,%1,%2,%3}, [%4];"
               : "=r"(r[0]), "=r"(r[1]), "=r"(r[2]), "=r"(r[3]) : "r"(addr));
}

__device__ __forceinline__ void mma_f16(float* c, const uint32_t* a,
                                        uint32_t b0, uint32_t b1) {
  asm volatile(
      "mma.sync.aligned.m16n8k16.row.col.f32.f16.f16.f32 "
      "{%0,%1,%2,%3}, {%4,%5,%6,%7}, {%8,%9}, {%0,%1,%2,%3};"
      : "+f"(c[0]), "+f"(c[1]), "+f"(c[2]), "+f"(c[3])
      : "r"(a[0]), "r"(a[1]), "r"(a[2]), "r"(a[3]), "r"(b0), "r"(b1));
}

__device__ __forceinline__ void cp16(uint32_t smem_addr, const void* gmem,
                                     uint32_t src_bytes) {
  asm volatile("cp.async.cg.shared.global [%0], [%1], 16, %2;"
               :: "r"(smem_addr), "l"(gmem), "r"(src_bytes) : "memory");
}

#define CP_COMMIT() asm volatile("cp.async.commit_group;" ::: "memory")
#define CP_WAIT2()  asm volatile("cp.async.wait_group 2;" ::: "memory")

// ---------------------------------------------------------------------------
// Kernel 1: merged prepass (unchanged from R14)
// ---------------------------------------------------------------------------

__global__ void __launch_bounds__(256)
prep_kernel(const float* __restrict__ x, const int* __restrict__ qw,
            const float* __restrict__ snz) {
  const int tid = threadIdx.x;
  const int b   = blockIdx.x;

  if (b < kDqBlocks) {
    const int e   = b >> 9;
    const int rem = b & 511;
    const int k0  = (rem >> 1) * 8;
    const int n   = ((rem & 1) * 256 + tid) * 4;
    const int g   = k0 >> 6;

    const float* sp = snz + (((size_t)e * kG + g) * kOUT + n) * 2;
    const float4 sa = *(const float4*)(sp);
    const float4 sb = *(const float4*)(sp + 4);
    const float s0 = sa.x, zp0 = fmaf(-8.f, sa.x, sa.y);
    const float s1 = sa.z, zp1 = fmaf(-8.f, sa.z, sa.w);
    const float s2 = sb.x, zp2 = fmaf(-8.f, sb.x, sb.y);
    const float s3 = sb.z, zp3 = fmaf(-8.f, sb.z, sb.w);

#pragma unroll
    for (int j = 0; j < 8; j++) {
      const size_t row = (size_t)e * kIN + k0 + j;
      const int4 q = *(const int4*)(qw + row * kOUT + n);
      uint2 o;
      o.x = pack_f16x2(fmaf((float)q.x, s0, zp0), fmaf((float)q.y, s1, zp1));
      o.y = pack_f16x2(fmaf((float)q.z, s2, zp2), fmaf((float)q.w, s3, zp3));
      *(uint2*)(&g_W[row * kOUT + n]) = o;
    }
  } else {
    const size_t base = ((size_t)(b - kDqBlocks) * 256 + tid) * 16;
#pragma unroll
    for (int i = 0; i < 4; i++) {
      const float4 v = *(const float4*)(x + base + i * 4);
      uint2 o;
      o.x = pack_f16x2(v.x, v.y);
      o.y = pack_f16x2(v.z, v.w);
      *(uint2*)(&g_xh[base + i * 4]) = o;
    }
  }
}

// ---------------------------------------------------------------------------
// Kernel 2: main GEMM
// ---------------------------------------------------------------------------

__global__ void __launch_bounds__(kThreads, 2)
hqq_mma_kernel(const int* __restrict__ tpe, float* __restrict__ out) {
  extern __shared__ __align__(1024) char smem[];
  const int tid = threadIdx.x;
  const int wid = tid >> 5;
  const int l   = tid & 31;

  const int e  = blockIdx.z;
  const int nt = blockIdx.x;
  const int mt = blockIdx.y;

  int off = 0, cnt = 0;
#pragma unroll
  for (int i = 0; i < kE; i++) {
    int c = __ldg(&tpe[i]);
    if (i < e) off += c;
    if (i == e) cnt = c;
  }
  if (mt * kBM >= cnt) return;

  const int row0  = off + mt * kBM;
  const int nrows = min(kBM, cnt - mt * kBM);
  const int n0    = nt * kBN;

  const uint32_t sbase = smem_u32(smem);

  // ---- fragment addressing (warp grid 2x4, warp tile 32x64) ----
  const int wm = wid >> 2;                 // 0..1
  const int wn = wid & 3;                  // 0..3
  const int bj = l & 7;
  const int segA4 = l >> 4;                // 0/1: fragment 16B column half

  // A: 64B rows, chunk x of row m stored at slot (x + (m>>1)) & 3
  uint32_t aRowB[2];
  int aHalf[2];
#pragma unroll
  for (int mi = 0; mi < 2; mi++) {
    const int row = wm * 32 + (l & 15) + mi * 16;
    aRowB[mi] = (uint32_t)(row * kARowB);
    aHalf[mi] = (row >> 1) & 3;
  }

  const int bkoff = ((l >> 3) & 1) * 8 + bj;      // k row offset within 16-k
  uint32_t bChunk[4];
#pragma unroll
  for (int ni2 = 0; ni2 < 4; ni2++)
    bChunk[ni2] = (uint32_t)(((wn * 8 + ni2 * 2 + (l >> 4)) ^ bj) * 16);

  const __half* xh_base = &g_xh[0];
  const __half* w_base  = &g_W[(size_t)e * kIN * kOUT];

  // cp.async invariants
  const int cpAm = tid >> 2, cpAx = tid & 3;          // A: 1 seg/thread
  const uint32_t cpAslot = (uint32_t)(((cpAx + (cpAm >> 1)) & 3) * 16);

  auto issue_stage = [&](int ch, uint32_t st) {
    const int k0 = ch * kBK;
    // A: 256 segs, row m (64B), slot swizzle
    cp16(st + (uint32_t)(cpAm * kARowB) + cpAslot,
         xh_base + (size_t)(row0 + cpAm) * kIN + k0 + cpAx * 8,
         (cpAm < nrows) ? 16u : 0u);
    // B: 1024 segs: g = i*256+tid -> krow = g>>5, nchunk = g&31
    const uint32_t stB = st + kATileB;
#pragma unroll
    for (int i = 0; i < 4; i++) {
      const int g = i * 256 + tid;
      const int krow = g >> 5, nchunk = g & 31;
      cp16(stB + (uint32_t)(krow * kBRowB + ((nchunk ^ (krow & 7)) * 16)),
           w_base + (size_t)(k0 + krow) * kOUT + n0 + nchunk * 8, 16u);
    }
    CP_COMMIT();
  };

  float mast[64];
#pragma unroll
  for (int i = 0; i < 64; i++) mast[i] = 0.f;

  auto compute_stage = [&](uint32_t base) {
    const uint32_t baseB = base + kATileB + (uint32_t)(bkoff * kBRowB);
#pragma unroll
    for (int ks = 0; ks < 2; ks++) {        // two 16-k steps per 32-k chunk
      uint32_t Af[2][4];
      const int x = ks * 2 + segA4;
#pragma unroll
      for (int mi = 0; mi < 2; mi++)
        ldsm_x4(Af[mi], base + aRowB[mi] +
                         (uint32_t)(((x + aHalf[mi]) & 3) * 16));
      const uint32_t bK = baseB + (uint32_t)(ks * 16 * kBRowB);
#pragma unroll
      for (int ni2 = 0; ni2 < 4; ni2++) {
        uint32_t r[4];
        ldsm_x4_trans(r, bK + bChunk[ni2]);
#pragma unroll
        for (int mi = 0; mi < 2; mi++) {
          mma_f16(&mast[(mi * 8 + ni2 * 2) * 4],     Af[mi], r[0], r[1]);
          mma_f16(&mast[(mi * 8 + ni2 * 2 + 1) * 4], Af[mi], r[2], r[3]);
        }
      }
    }
  };

  // ---- 4-stage ring, prefetch depth 3 (wait_group<2>) ----
  issue_stage(0, sbase);
  issue_stage(1, sbase + kStageB);
  issue_stage(2, sbase + 2 * kStageB);

  for (int ch = 0; ch < kNCh; ch++) {
    CP_WAIT2();                 // stage ch landed (<=2 younger pending)
    __syncthreads();            // visible to all; compute(ch-1) done -> ring slot free
    if (ch + 3 < kNCh) issue_stage(ch + 3, sbase + ((ch + 3) & 3) * kStageB);
    else CP_COMMIT();           // empty group keeps wait accounting uniform
    compute_stage(sbase + (ch & 3) * kStageB);
  }

  // ---- epilogue ----
#pragma unroll
  for (int mi = 0; mi < 2; mi++) {
#pragma unroll
    for (int ni = 0; ni < 8; ni++) {
      const float* c = &mast[(mi * 8 + ni) * 4];
      const int r0  = wm * 32 + mi * 16 + (l >> 2);
      const int col = n0 + wn * 64 + ni * 8 + (l & 3) * 2;
      if (r0 < nrows)
        *(float2*)(out + (size_t)(row0 + r0) * kOUT + col) = make_float2(c[0], c[1]);
      if (r0 + 8 < nrows)
        *(float2*)(out + (size_t)(row0 + r0 + 8) * kOUT + col) = make_float2(c[2], c[3]);
    }
  }
}

}  // namespace

// ---------------------------------------------------------------------------

extern "C" void kernel_launch(void* const* d_in, const int* in_sizes, int n_in,
                              void* d_out, int out_size) {
  (void)in_sizes; (void)n_in; (void)out_size;
  const float* x   = (const float*)d_in[0];
  const int*   qw  = (const int*)d_in[1];
  const float* snz = (const float*)d_in[2];
  const int*   tpe = (const int*)d_in[3];
  float* out = (float*)d_out;

  (void)cudaFuncSetAttribute(hqq_mma_kernel,
                             cudaFuncAttributeMaxDynamicSharedMemorySize, kSmemB);

  prep_kernel<<<kDqBlocks + kCvBlocks, 256>>>(x, qw, snz);
  dim3 grid(kOUT / kBN, kT / kBM, kE);   // (8, 32, 8); empty m-tiles early-exit
  hqq_mma_kernel<<<grid, kThreads, kSmemB>>>(tpe, out);
}